// round 11
// baseline (speedup 1.0000x reference)
#include <cuda_runtime.h>
#include <cuda_fp16.h>
#include <math.h>
#include <stdint.h>

#define Bsz   2
#define Sseq  2048
#define Dm    1024
#define Hh    16
#define DHd   64
#define BLKs  128
#define NBl   16
#define Mrows (Bsz * Sseq)   // 4096
#define Dff   (4 * Dm)       // 4096
#define QKV3  (3 * Dm)       // 3072

// ---------------- scratch ---------------------------------------------------
__device__ __half g_h   [Mrows * Dm];
__device__ __half g_qkv [Mrows * QKV3];
__device__ __half g_ctx [Mrows * Dm];
__device__ float  g_x1  [Mrows * Dm];
__device__ __half g_h2  [Mrows * Dm];
__device__ __half g_ff  [Mrows * Dff];
__device__ __half g_wqkv[QKV3 * Dm];    // [n][k]
__device__ __half g_wo  [Dm * Dm];
__device__ __half g_w1  [Dff * Dm];
__device__ __half g_w2  [Dm * Dff];
__device__ float  g_bqkv[QKV3];

// ---------------- helpers ---------------------------------------------------
__device__ __forceinline__ uint32_t smem_u32(const void* p) {
    uint32_t a;
    asm("{ .reg .u64 t; cvta.to.shared.u64 t, %1; cvt.u32.u64 %0, t; }"
        : "=r"(a) : "l"(p));
    return a;
}
__device__ __forceinline__ uint32_t h2_as_u32(__half2 h) {
    return *reinterpret_cast<uint32_t*>(&h);
}
__device__ __forceinline__ void cpa16(uint32_t dst, const void* src) {
    asm volatile("cp.async.cg.shared.global [%0], [%1], 16;" :: "r"(dst), "l"(src));
}
__device__ __forceinline__ float gelu_exact(float x) {
    return 0.5f * x * (1.0f + erff(x * 0.70710678118654752f));
}
__device__ __forceinline__ void ldsm4(uint32_t addr, uint32_t& r0, uint32_t& r1,
                                      uint32_t& r2, uint32_t& r3) {
    asm volatile("ldmatrix.sync.aligned.m8n8.x4.shared.b16 {%0,%1,%2,%3}, [%4];"
                 : "=r"(r0), "=r"(r1), "=r"(r2), "=r"(r3) : "r"(addr));
}
__device__ __forceinline__ void ldsm4t(uint32_t addr, uint32_t& r0, uint32_t& r1,
                                       uint32_t& r2, uint32_t& r3) {
    asm volatile("ldmatrix.sync.aligned.m8n8.x4.trans.shared.b16 {%0,%1,%2,%3}, [%4];"
                 : "=r"(r0), "=r"(r1), "=r"(r2), "=r"(r3) : "r"(addr));
}
#define MMA16816(acc, a0, a1, a2, a3, b0, b1)                                   \
    asm volatile("mma.sync.aligned.m16n8k16.row.col.f32.f16.f16.f32 "           \
                 "{%0,%1,%2,%3}, {%4,%5,%6,%7}, {%8,%9}, {%0,%1,%2,%3};"        \
                 : "+f"((acc)[0]), "+f"((acc)[1]), "+f"((acc)[2]), "+f"((acc)[3])\
                 : "r"(a0), "r"(a1), "r"(a2), "r"(a3), "r"(b0), "r"(b1))

// ---------------- weight prep: W[k][n] f32 -> Wh[rowOff+n][k] half ----------
__global__ __launch_bounds__(256) void wtrans(
    const float* __restrict__ W, __half* __restrict__ Wh,
    int K, int N, int rowOff)
{
    __shared__ __half t[32][33];
    const int nb = blockIdx.x * 32, kb = blockIdx.y * 32;
    const int tx = threadIdx.x & 31, ty = threadIdx.x >> 5;
    #pragma unroll
    for (int i = 0; i < 32; i += 8)
        t[ty + i][tx] = __float2half(W[(size_t)(kb + ty + i) * N + nb + tx]);
    __syncthreads();
    #pragma unroll
    for (int i = 0; i < 32; i += 8)
        Wh[(size_t)(rowOff + nb + ty + i) * K + kb + tx] = t[tx][ty + i];
}

__global__ __launch_bounds__(256) void bprep(
    const float* __restrict__ bq, const float* __restrict__ bk,
    const float* __restrict__ bv, float* __restrict__ dst)
{
    const int i = blockIdx.x * 256 + threadIdx.x;
    if (i >= QKV3) return;
    dst[i] = (i < Dm) ? bq[i] : (i < 2 * Dm) ? bk[i - Dm] : bv[i - 2 * Dm];
}

// ---------------- fp16 mma.sync GEMM : CTA 256x128, warp 64x64 --------------
// EPI: 0=+bias->f32 ; 1=+bias,gelu->half ; 2=+bias,+res->f32 ; 3=+bias->half
#define ROWB  80                          // smem row stride bytes (40 halves)
#define AOPB  (256 * ROWB)                // 20480
#define BOPB  (128 * ROWB)                // 10240
#define STAGE (AOPB + BOPB)               // 30720
#define NSTG  4
#define MMA_SMEM (NSTG * STAGE)           // 122880

template<int EPI>
__global__ __launch_bounds__(256, 1) void mma_gemm(
    const __half* __restrict__ A, const __half* __restrict__ B,
    const float* __restrict__ bias, const float* __restrict__ res,
    void* __restrict__ Cv, int M, int N, int K)
{
    extern __shared__ char smem[];
    const uint32_t sbase = smem_u32(smem);
    const int tid = threadIdx.x;
    const int bm  = blockIdx.y * 256;
    const int bn  = blockIdx.x * 128;
    const int NK  = K >> 5;

    // cp.async: A row = tid (4x16B) ; B row = tid>>1, segs (tid&1)*2+{0,1}
    const int brow = tid >> 1;
    const int bs0  = (tid & 1) * 2;
    const char* Ag = reinterpret_cast<const char*>(A) + (size_t)(bm + tid) * K * 2;
    const char* Bg = reinterpret_cast<const char*>(B) + (size_t)(bn + brow) * K * 2;

    #define ISSUE_CHUNK(kt, st)                                                 \
    {   const uint32_t ab = sbase + (st) * STAGE + tid * ROWB;                  \
        const char* agp = Ag + (size_t)(kt) * 64;                               \
        cpa16(ab,      agp);                                                    \
        cpa16(ab + 16, agp + 16);                                               \
        cpa16(ab + 32, agp + 32);                                               \
        cpa16(ab + 48, agp + 48);                                               \
        const uint32_t bb = sbase + (st) * STAGE + AOPB + brow * ROWB;          \
        const char* bgp = Bg + (size_t)(kt) * 64;                               \
        cpa16(bb + bs0 * 16,       bgp + bs0 * 16);                             \
        cpa16(bb + (bs0 + 1) * 16, bgp + (bs0 + 1) * 16);                       \
        asm volatile("cp.async.commit_group;" ::: "memory");                    \
    }

    const int w    = tid >> 5, lane = tid & 31;
    const int wm   = (w >> 1) * 64;       // 4 row groups
    const int wn   = (w & 1) * 64;        // 2 col groups
    const int lt   = lane >> 3;
    const int lrow = lane & 7;

    float acc[4][8][4];
    #pragma unroll
    for (int i = 0; i < 4; i++)
        #pragma unroll
        for (int j = 0; j < 8; j++)
            #pragma unroll
            for (int c = 0; c < 4; c++) acc[i][j][c] = 0.f;

    ISSUE_CHUNK(0, 0);
    ISSUE_CHUNK(1, 1);
    ISSUE_CHUNK(2, 2);

    for (int kt = 0; kt < NK; kt++) {
        const int st = kt & (NSTG - 1);
        asm volatile("cp.async.wait_group 2;" ::: "memory");
        __syncthreads();
        if (kt + 3 < NK) {
            ISSUE_CHUNK(kt + 3, (kt + 3) & (NSTG - 1));
        } else {
            asm volatile("cp.async.commit_group;" ::: "memory");
        }

        const uint32_t as = sbase + st * STAGE;
        const uint32_t bs = as + AOPB;

        #pragma unroll
        for (int ks = 0; ks < 2; ks++) {
            uint32_t a[4][4];
            #pragma unroll
            for (int i = 0; i < 4; i++) {
                const uint32_t addr = as
                    + (uint32_t)(wm + i * 16 + (lt & 1) * 8 + lrow) * ROWB
                    + ks * 32 + (lt >> 1) * 16;
                ldsm4(addr, a[i][0], a[i][1], a[i][2], a[i][3]);
            }
            uint32_t b[8][2];
            #pragma unroll
            for (int jp = 0; jp < 4; jp++) {
                const uint32_t addr = bs
                    + (uint32_t)(wn + jp * 16 + (lt >> 1) * 8 + lrow) * ROWB
                    + ks * 32 + (lt & 1) * 16;
                ldsm4(addr, b[2 * jp][0], b[2 * jp][1],
                            b[2 * jp + 1][0], b[2 * jp + 1][1]);
            }
            #pragma unroll
            for (int i = 0; i < 4; i++)
                #pragma unroll
                for (int j = 0; j < 8; j++)
                    MMA16816(acc[i][j], a[i][0], a[i][1], a[i][2], a[i][3],
                             b[j][0], b[j][1]);
        }
    }
    #undef ISSUE_CHUNK

    const int lr = lane >> 2;
    const int lk = lane & 3;
    #pragma unroll
    for (int i = 0; i < 4; i++) {
        #pragma unroll
        for (int j = 0; j < 8; j++) {
            const int row0 = bm + wm + i * 16 + lr;
            const int col  = bn + wn + j * 8 + lk * 2;
            #pragma unroll
            for (int hrow = 0; hrow < 2; hrow++) {
                const int row = row0 + hrow * 8;
                float ox = acc[i][j][hrow * 2 + 0] + bias[col + 0];
                float oy = acc[i][j][hrow * 2 + 1] + bias[col + 1];
                if (EPI == 1 || EPI == 3) {
                    if (EPI == 1) { ox = gelu_exact(ox); oy = gelu_exact(oy); }
                    __half2* dst = reinterpret_cast<__half2*>(
                        reinterpret_cast<__half*>(Cv) + (size_t)row * N + col);
                    *dst = __floats2half2_rn(ox, oy);
                } else {
                    if (EPI == 2) {
                        const float2 r2 = *reinterpret_cast<const float2*>(
                            res + (size_t)row * N + col);
                        ox += r2.x; oy += r2.y;
                    }
                    float2 o; o.x = ox; o.y = oy;
                    *reinterpret_cast<float2*>(
                        reinterpret_cast<float*>(Cv) + (size_t)row * N + col) = o;
                }
            }
        }
    }
}

// ---------------- LayerNorm (half output) -----------------------------------
__global__ __launch_bounds__(256) void ln_kernel(
    const float* __restrict__ x, const float* __restrict__ g,
    const float* __restrict__ b, __half* __restrict__ out)
{
    const int row = blockIdx.x;
    const int t   = threadIdx.x;
    const float4 v = reinterpret_cast<const float4*>(x + (size_t)row * Dm)[t];

    float s  = v.x + v.y + v.z + v.w;
    float s2 = v.x * v.x + v.y * v.y + v.z * v.z + v.w * v.w;

    __shared__ float red[16];
    #pragma unroll
    for (int o = 16; o; o >>= 1) {
        s  += __shfl_xor_sync(0xffffffffu, s,  o);
        s2 += __shfl_xor_sync(0xffffffffu, s2, o);
    }
    const int w = t >> 5, l = t & 31;
    if (l == 0) { red[w] = s; red[w + 8] = s2; }
    __syncthreads();
    if (w == 0) {
        float a  = (l < 8) ? red[l]     : 0.f;
        float a2 = (l < 8) ? red[l + 8] : 0.f;
        #pragma unroll
        for (int o = 4; o; o >>= 1) {
            a  += __shfl_xor_sync(0xffffffffu, a,  o);
            a2 += __shfl_xor_sync(0xffffffffu, a2, o);
        }
        if (l == 0) { red[0] = a; red[1] = a2; }
    }
    __syncthreads();

    const float mean = red[0] * (1.f / Dm);
    const float var  = red[1] * (1.f / Dm) - mean * mean;
    const float rs   = rsqrtf(var + 1e-5f);

    const float4 gg = reinterpret_cast<const float4*>(g)[t];
    const float4 bb = reinterpret_cast<const float4*>(b)[t];
    const float o0 = (v.x - mean) * rs * gg.x + bb.x;
    const float o1 = (v.y - mean) * rs * gg.y + bb.y;
    const float o2 = (v.z - mean) * rs * gg.z + bb.z;
    const float o3 = (v.w - mean) * rs * gg.w + bb.w;

    __half2* dst = reinterpret_cast<__half2*>(out + (size_t)row * Dm) + t * 2;
    dst[0] = __floats2half2_rn(o0, o1);
    dst[1] = __floats2half2_rn(o2, o3);
}

// ---------------- tensor-core block-sparse flash attention ------------------
#define QST 72   // smem row stride in halves (144 B)
#define ATTN_SMEM (3 * 128 * QST * 2)

__global__ __launch_bounds__(256) void attn_kernel(
    const __half* __restrict__ qkv, const int* __restrict__ layout,
    __half* __restrict__ ctx)
{
    extern __shared__ __half smh[];
    __half* sQ = smh;
    __half* sK = smh + 128 * QST;
    __half* sV = smh + 256 * QST;
    const uint32_t sQa = smem_u32(sQ);
    const uint32_t sKa = smem_u32(sK);
    const uint32_t sVa = smem_u32(sV);

    const int ib  = blockIdx.x;
    const int hh  = blockIdx.y;
    const int bb  = blockIdx.z;
    const int tid = threadIdx.x;
    const int w    = tid >> 5, lane = tid & 31;
    const int lr   = lane >> 2, lk = lane & 3;
    const int lt   = lane >> 3, lrow = lane & 7;
    const int wm   = w * 16;

    const size_t qrow0 = (size_t)(bb * Sseq + ib * BLKs);

    for (int f = tid; f < 1024; f += 256) {
        const int row = f >> 3, seg = f & 7;
        *reinterpret_cast<uint4*>(sQ + row * QST + seg * 8) =
            *reinterpret_cast<const uint4*>(qkv + (qrow0 + row) * QKV3 + hh * 64 + seg * 8);
    }
    __syncthreads();

    uint32_t qf[4][4];
    #pragma unroll
    for (int ks = 0; ks < 4; ks++) {
        const uint32_t addr = sQa + (uint32_t)(wm + (lt & 1) * 8 + lrow) * 144
                            + ks * 32 + (lt >> 1) * 16;
        ldsm4(addr, qf[ks][0], qf[ks][1], qf[ks][2], qf[ks][3]);
    }

    float m0 = -1e30f, m1 = -1e30f, l0 = 0.f, l1 = 0.f;
    float octx[8][4];
    #pragma unroll
    for (int jn = 0; jn < 8; jn++)
        #pragma unroll
        for (int c = 0; c < 4; c++) octx[jn][c] = 0.f;

    for (int j = 0; j <= ib; j++) {
        if (!layout[(hh * NBl + ib) * NBl + j]) continue;

        __syncthreads();
        const size_t krow0 = (size_t)(bb * Sseq + j * BLKs);
        for (int f = tid; f < 1024; f += 256) {
            const int row = f >> 3, seg = f & 7;
            const __half* src = qkv + (krow0 + row) * QKV3 + hh * 64 + seg * 8;
            *reinterpret_cast<uint4*>(sK + row * QST + seg * 8) =
                *reinterpret_cast<const uint4*>(src + Dm);
            *reinterpret_cast<uint4*>(sV + row * QST + seg * 8) =
                *reinterpret_cast<const uint4*>(src + 2 * Dm);
        }
        __syncthreads();

        float sacc[16][4];
        #pragma unroll
        for (int jf = 0; jf < 16; jf++)
            #pragma unroll
            for (int c = 0; c < 4; c++) sacc[jf][c] = 0.f;

        #pragma unroll
        for (int ks = 0; ks < 4; ks++) {
            #pragma unroll
            for (int jp = 0; jp < 8; jp++) {
                uint32_t b0, b1, b2, b3;
                const uint32_t addr = sKa
                    + (uint32_t)(jp * 16 + (lt >> 1) * 8 + lrow) * 144
                    + ks * 32 + (lt & 1) * 16;
                ldsm4(addr, b0, b1, b2, b3);
                MMA16816(sacc[2 * jp],     qf[ks][0], qf[ks][1], qf[ks][2], qf[ks][3], b0, b1);
                MMA16816(sacc[2 * jp + 1], qf[ks][0], qf[ks][1], qf[ks][2], qf[ks][3], b2, b3);
            }
        }

        const int r0 = wm + lr, r1 = wm + lr + 8;
        #pragma unroll
        for (int jf = 0; jf < 16; jf++) {
            #pragma unroll
            for (int c = 0; c < 4; c++) sacc[jf][c] *= 0.125f;
            if (j == ib) {
                const int c0 = jf * 8 + lk * 2, c1 = c0 + 1;
                if (c0 > r0) sacc[jf][0] = -1e9f;
                if (c1 > r0) sacc[jf][1] = -1e9f;
                if (c0 > r1) sacc[jf][2] = -1e9f;
                if (c1 > r1) sacc[jf][3] = -1e9f;
            }
        }

        float bm0 = -1e30f, bm1 = -1e30f;
        #pragma unroll
        for (int jf = 0; jf < 16; jf++) {
            bm0 = fmaxf(bm0, fmaxf(sacc[jf][0], sacc[jf][1]));
            bm1 = fmaxf(bm1, fmaxf(sacc[jf][2], sacc[jf][3]));
        }
        bm0 = fmaxf(bm0, __shfl_xor_sync(0xffffffffu, bm0, 1));
        bm0 = fmaxf(bm0, __shfl_xor_sync(0xffffffffu, bm0, 2));
        bm1 = fmaxf(bm1, __shfl_xor_sync(0xffffffffu, bm1, 1));
        bm1 = fmaxf(bm1, __shfl_xor_sync(0xffffffffu, bm1, 2));

        const float nm0 = fmaxf(m0, bm0), nm1 = fmaxf(m1, bm1);
        const float cr0 = __expf(m0 - nm0), cr1 = __expf(m1 - nm1);

        float s0 = 0.f, s1 = 0.f;
        uint32_t ph[16][2];
        #pragma unroll
        for (int jf = 0; jf < 16; jf++) {
            const float p00 = __expf(sacc[jf][0] - nm0);
            const float p01 = __expf(sacc[jf][1] - nm0);
            const float p10 = __expf(sacc[jf][2] - nm1);
            const float p11 = __expf(sacc[jf][3] - nm1);
            s0 += p00 + p01; s1 += p10 + p11;
            ph[jf][0] = h2_as_u32(__floats2half2_rn(p00, p01));
            ph[jf][1] = h2_as_u32(__floats2half2_rn(p10, p11));
        }
        s0 += __shfl_xor_sync(0xffffffffu, s0, 1);
        s0 += __shfl_xor_sync(0xffffffffu, s0, 2);
        s1 += __shfl_xor_sync(0xffffffffu, s1, 1);
        s1 += __shfl_xor_sync(0xffffffffu, s1, 2);

        l0 = l0 * cr0 + s0;
        l1 = l1 * cr1 + s1;
        #pragma unroll
        for (int jn = 0; jn < 8; jn++) {
            octx[jn][0] *= cr0; octx[jn][1] *= cr0;
            octx[jn][2] *= cr1; octx[jn][3] *= cr1;
        }

        #pragma unroll
        for (int kk = 0; kk < 8; kk++) {
            const uint32_t a0 = ph[2 * kk][0],     a1 = ph[2 * kk][1];
            const uint32_t a2 = ph[2 * kk + 1][0], a3 = ph[2 * kk + 1][1];
            #pragma unroll
            for (int jp = 0; jp < 4; jp++) {
                uint32_t b0, b1, b2, b3;
                const uint32_t addr = sVa
                    + (uint32_t)(kk * 16 + (lt & 1) * 8 + lrow) * 144
                    + (uint32_t)(jp * 16 + (lt >> 1) * 8) * 2;
                ldsm4t(addr, b0, b1, b2, b3);
                MMA16816(octx[2 * jp],     a0, a1, a2, a3, b0, b1);
                MMA16816(octx[2 * jp + 1], a0, a1, a2, a3, b2, b3);
            }
        }
        m0 = nm0; m1 = nm1;
    }

    const float inv0 = 1.f / l0, inv1 = 1.f / l1;
    __half* base0 = ctx + (qrow0 + wm + lr) * Dm + hh * 64;
    __half* base1 = ctx + (qrow0 + wm + lr + 8) * Dm + hh * 64;
    #pragma unroll
    for (int jn = 0; jn < 8; jn++) {
        const int col = jn * 8 + lk * 2;
        *reinterpret_cast<__half2*>(base0 + col) =
            __floats2half2_rn(octx[jn][0] * inv0, octx[jn][1] * inv0);
        *reinterpret_cast<__half2*>(base1 + col) =
            __floats2half2_rn(octx[jn][2] * inv1, octx[jn][3] * inv1);
    }
}

// ---------------------------------------------------------------------------
extern "C" void kernel_launch(void* const* d_in, const int* in_sizes, int n_in,
                              void* d_out, int out_size)
{
    (void)in_sizes; (void)n_in; (void)out_size;
    const float* x     = (const float*)d_in[0];
    const float* ln1_g = (const float*)d_in[1];
    const float* ln1_b = (const float*)d_in[2];
    const float* Wq    = (const float*)d_in[3];
    const float* bq    = (const float*)d_in[4];
    const float* Wk    = (const float*)d_in[5];
    const float* bk    = (const float*)d_in[6];
    const float* Wv    = (const float*)d_in[7];
    const float* bv    = (const float*)d_in[8];
    const float* Wo    = (const float*)d_in[9];
    const float* bo    = (const float*)d_in[10];
    const float* ln2_g = (const float*)d_in[11];
    const float* ln2_b = (const float*)d_in[12];
    const float* W1    = (const float*)d_in[13];
    const float* b1    = (const float*)d_in[14];
    const float* W2    = (const float*)d_in[15];
    const float* b2    = (const float*)d_in[16];
    const int*   lay   = (const int*)d_in[17];
    float* out = (float*)d_out;

    __half *h, *qkv, *ctx, *h2, *ff, *wqkv, *wo, *w1, *w2;
    float  *x1, *bqkv;
    cudaGetSymbolAddress((void**)&h,    g_h);
    cudaGetSymbolAddress((void**)&qkv,  g_qkv);
    cudaGetSymbolAddress((void**)&ctx,  g_ctx);
    cudaGetSymbolAddress((void**)&x1,   g_x1);
    cudaGetSymbolAddress((void**)&h2,   g_h2);
    cudaGetSymbolAddress((void**)&ff,   g_ff);
    cudaGetSymbolAddress((void**)&wqkv, g_wqkv);
    cudaGetSymbolAddress((void**)&wo,   g_wo);
    cudaGetSymbolAddress((void**)&w1,   g_w1);
    cudaGetSymbolAddress((void**)&w2,   g_w2);
    cudaGetSymbolAddress((void**)&bqkv, g_bqkv);

    cudaFuncSetAttribute(attn_kernel,
                         cudaFuncAttributeMaxDynamicSharedMemorySize, ATTN_SMEM);
    cudaFuncSetAttribute(mma_gemm<1>,
                         cudaFuncAttributeMaxDynamicSharedMemorySize, MMA_SMEM);
    cudaFuncSetAttribute(mma_gemm<2>,
                         cudaFuncAttributeMaxDynamicSharedMemorySize, MMA_SMEM);
    cudaFuncSetAttribute(mma_gemm<3>,
                         cudaFuncAttributeMaxDynamicSharedMemorySize, MMA_SMEM);

    // 0) weight prep
    wtrans<<<dim3(Dm / 32, Dm / 32), 256>>>(Wq, wqkv, Dm, Dm, 0);
    wtrans<<<dim3(Dm / 32, Dm / 32), 256>>>(Wk, wqkv, Dm, Dm, Dm);
    wtrans<<<dim3(Dm / 32, Dm / 32), 256>>>(Wv, wqkv, Dm, Dm, 2 * Dm);
    wtrans<<<dim3(Dm / 32, Dm / 32), 256>>>(Wo, wo, Dm, Dm, 0);
    wtrans<<<dim3(Dff / 32, Dm / 32), 256>>>(W1, w1, Dm, Dff, 0);
    wtrans<<<dim3(Dm / 32, Dff / 32), 256>>>(W2, w2, Dff, Dm, 0);
    bprep<<<(QKV3 + 255) / 256, 256>>>(bq, bk, bv, bqkv);

    // 1) ln1 -> half h
    ln_kernel<<<Mrows, 256>>>(x, ln1_g, ln1_b, h);

    // 2) fused QKV projection (half out)
    mma_gemm<3><<<dim3(QKV3 / 128, Mrows / 256), 256, MMA_SMEM>>>(
        h, wqkv, bqkv, nullptr, qkv, Mrows, QKV3, Dm);

    // 3) tensor-core block-sparse attention -> half ctx
    attn_kernel<<<dim3(NBl, Hh, Bsz), 256, ATTN_SMEM>>>(qkv, lay, ctx);

    // 4) output projection + residual (float x1)
    dim3 g1(Dm / 128, Mrows / 256);
    mma_gemm<2><<<g1, 256, MMA_SMEM>>>(ctx, wo, bo, x, x1, Mrows, Dm, Dm);

    // 5) ln2 -> half h2
    ln_kernel<<<Mrows, 256>>>(x1, ln2_g, ln2_b, h2);

    // 6) MLP
    dim3 g2(Dff / 128, Mrows / 256);
    mma_gemm<1><<<g2, 256, MMA_SMEM>>>(h2, w1, b1, nullptr, ff, Mrows, Dff, Dm);
    mma_gemm<2><<<g1, 256, MMA_SMEM>>>(ff, w2, b2, x1, out, Mrows, Dm, Dff);
}

// round 16
// speedup vs baseline: 1.2153x; 1.2153x over previous
#include <cuda_runtime.h>
#include <cuda_fp16.h>
#include <math.h>
#include <stdint.h>

#define Bsz   2
#define Sseq  2048
#define Dm    1024
#define Hh    16
#define DHd   64
#define BLKs  128
#define NBl   16
#define Mrows (Bsz * Sseq)   // 4096
#define Dff   (4 * Dm)       // 4096
#define QKV3  (3 * Dm)       // 3072

// ---------------- scratch ---------------------------------------------------
__device__ __half g_h   [Mrows * Dm];
__device__ __half g_qkv [Mrows * QKV3];
__device__ __half g_ctx [Mrows * Dm];
__device__ float  g_x1  [Mrows * Dm];
__device__ __half g_h2  [Mrows * Dm];
__device__ __half g_ff  [Mrows * Dff];
__device__ __half g_wqkv[QKV3 * Dm];    // [n][k]
__device__ __half g_wo  [Dm * Dm];
__device__ __half g_w1  [Dff * Dm];
__device__ __half g_w2  [Dm * Dff];
__device__ float  g_bqkv[QKV3];

// ---------------- helpers ---------------------------------------------------
__device__ __forceinline__ uint32_t smem_u32(const void* p) {
    uint32_t a;
    asm("{ .reg .u64 t; cvta.to.shared.u64 t, %1; cvt.u32.u64 %0, t; }"
        : "=r"(a) : "l"(p));
    return a;
}
__device__ __forceinline__ uint32_t h2_as_u32(__half2 h) {
    return *reinterpret_cast<uint32_t*>(&h);
}
__device__ __forceinline__ void cpa16(uint32_t dst, const void* src) {
    asm volatile("cp.async.cg.shared.global [%0], [%1], 16;" :: "r"(dst), "l"(src));
}
__device__ __forceinline__ float gelu_exact(float x) {
    return 0.5f * x * (1.0f + erff(x * 0.70710678118654752f));
}
__device__ __forceinline__ void ldsm4(uint32_t addr, uint32_t& r0, uint32_t& r1,
                                      uint32_t& r2, uint32_t& r3) {
    asm volatile("ldmatrix.sync.aligned.m8n8.x4.shared.b16 {%0,%1,%2,%3}, [%4];"
                 : "=r"(r0), "=r"(r1), "=r"(r2), "=r"(r3) : "r"(addr));
}
__device__ __forceinline__ void ldsm4t(uint32_t addr, uint32_t& r0, uint32_t& r1,
                                       uint32_t& r2, uint32_t& r3) {
    asm volatile("ldmatrix.sync.aligned.m8n8.x4.trans.shared.b16 {%0,%1,%2,%3}, [%4];"
                 : "=r"(r0), "=r"(r1), "=r"(r2), "=r"(r3) : "r"(addr));
}
#define MMA16816(acc, a0, a1, a2, a3, b0, b1)                                   \
    asm volatile("mma.sync.aligned.m16n8k16.row.col.f32.f16.f16.f32 "           \
                 "{%0,%1,%2,%3}, {%4,%5,%6,%7}, {%8,%9}, {%0,%1,%2,%3};"        \
                 : "+f"((acc)[0]), "+f"((acc)[1]), "+f"((acc)[2]), "+f"((acc)[3])\
                 : "r"(a0), "r"(a1), "r"(a2), "r"(a3), "r"(b0), "r"(b1))

// ---------------- fused weight prep: all 6 transposes in one launch ----------
// tiles: [0,4096)  -> Wq/Wk/Wv/Wo (1024 each, K=N=1024)
//        [4096,8192) -> W1 (K=1024, N=4096)
//        [8192,12288) -> W2 (K=4096, N=1024)
__global__ __launch_bounds__(256) void wprep_all(
    const float* __restrict__ Wq, const float* __restrict__ Wk,
    const float* __restrict__ Wv, const float* __restrict__ Wo,
    const float* __restrict__ W1, const float* __restrict__ W2,
    __half* __restrict__ wqkv, __half* __restrict__ wo,
    __half* __restrict__ w1, __half* __restrict__ w2)
{
    const int t = blockIdx.x;
    const float* src; __half* dst;
    int K, N, rowOff, nb, kb;
    if (t < 4096) {
        const int wsel = t >> 10, tt = t & 1023;
        nb = (tt & 31) * 32; kb = (tt >> 5) * 32; K = 1024; N = 1024;
        if      (wsel == 0) { src = Wq; dst = wqkv; rowOff = 0;    }
        else if (wsel == 1) { src = Wk; dst = wqkv; rowOff = 1024; }
        else if (wsel == 2) { src = Wv; dst = wqkv; rowOff = 2048; }
        else                { src = Wo; dst = wo;   rowOff = 0;    }
    } else if (t < 8192) {
        const int tt = t - 4096;
        nb = (tt & 127) * 32; kb = (tt >> 7) * 32; K = 1024; N = 4096;
        src = W1; dst = w1; rowOff = 0;
    } else {
        const int tt = t - 8192;
        nb = (tt & 31) * 32; kb = (tt >> 5) * 32; K = 4096; N = 1024;
        src = W2; dst = w2; rowOff = 0;
    }

    __shared__ __half tile[32][33];
    const int tx = threadIdx.x & 31, ty = threadIdx.x >> 5;
    #pragma unroll
    for (int i = 0; i < 32; i += 8)
        tile[ty + i][tx] = __float2half(src[(size_t)(kb + ty + i) * N + nb + tx]);
    __syncthreads();
    #pragma unroll
    for (int i = 0; i < 32; i += 8)
        dst[(size_t)(rowOff + nb + ty + i) * K + kb + tx] = tile[tx][ty + i];
}

__global__ __launch_bounds__(256) void bprep(
    const float* __restrict__ bq, const float* __restrict__ bk,
    const float* __restrict__ bv, float* __restrict__ dst)
{
    const int i = blockIdx.x * 256 + threadIdx.x;
    if (i >= QKV3) return;
    dst[i] = (i < Dm) ? bq[i] : (i < 2 * Dm) ? bk[i - Dm] : bv[i - 2 * Dm];
}

// ---------------- fp16 mma.sync GEMM (proven 128x128, 2 CTA/SM) -------------
// EPI: 0=+bias->f32 ; 1=+bias,gelu->half ; 2=+bias,+res->f32 ; 3=+bias->half
#define AST   40
#define OPB   (128 * AST * 2)
#define STAGE (2 * OPB)
#define NSTG  4
#define MMA_SMEM (NSTG * STAGE)

template<int EPI>
__global__ __launch_bounds__(256, 2) void mma_gemm(
    const __half* __restrict__ A, const __half* __restrict__ B,
    const float* __restrict__ bias, const float* __restrict__ res,
    void* __restrict__ Cv, int M, int N, int K)
{
    extern __shared__ char smem[];
    const uint32_t sbase = smem_u32(smem);
    const int tid = threadIdx.x;
    const int bm  = blockIdx.y * 128;
    const int bn  = blockIdx.x * 128;
    const int NK  = K >> 5;

    const int crow = tid >> 1;
    const int cs0  = (tid & 1) * 2;
    const char* Ag = reinterpret_cast<const char*>(A) + (size_t)(bm + crow) * K * 2;
    const char* Bg = reinterpret_cast<const char*>(B) + (size_t)(bn + crow) * K * 2;

    #define ISSUE_CHUNK(kt, st)                                                 \
    {   const uint32_t ab = sbase + (st) * STAGE + crow * 80;                   \
        const char* agp = Ag + (size_t)(kt) * 64;                               \
        cpa16(ab + cs0 * 16,       agp + cs0 * 16);                             \
        cpa16(ab + (cs0 + 1) * 16, agp + (cs0 + 1) * 16);                       \
        const uint32_t bb = ab + OPB;                                           \
        const char* bgp = Bg + (size_t)(kt) * 64;                               \
        cpa16(bb + cs0 * 16,       bgp + cs0 * 16);                             \
        cpa16(bb + (cs0 + 1) * 16, bgp + (cs0 + 1) * 16);                       \
        asm volatile("cp.async.commit_group;" ::: "memory");                    \
    }

    const int w    = tid >> 5, lane = tid & 31;
    const int wm   = (w >> 2) * 64;
    const int wn   = (w & 3) * 32;
    const int lt   = lane >> 3;
    const int lrow = lane & 7;

    float acc[4][4][4];
    #pragma unroll
    for (int i = 0; i < 4; i++)
        #pragma unroll
        for (int j = 0; j < 4; j++)
            #pragma unroll
            for (int c = 0; c < 4; c++) acc[i][j][c] = 0.f;

    ISSUE_CHUNK(0, 0);
    ISSUE_CHUNK(1, 1);
    ISSUE_CHUNK(2, 2);

    for (int kt = 0; kt < NK; kt++) {
        const int st = kt & (NSTG - 1);
        asm volatile("cp.async.wait_group 2;" ::: "memory");
        __syncthreads();
        if (kt + 3 < NK) {
            ISSUE_CHUNK(kt + 3, (kt + 3) & (NSTG - 1));
        } else {
            asm volatile("cp.async.commit_group;" ::: "memory");
        }

        const uint32_t as = sbase + st * STAGE;
        const uint32_t bs = as + OPB;

        #pragma unroll
        for (int ks = 0; ks < 2; ks++) {
            uint32_t a[4][4];
            #pragma unroll
            for (int i = 0; i < 4; i++) {
                const uint32_t addr = as
                    + (uint32_t)(wm + i * 16 + (lt & 1) * 8 + lrow) * 80
                    + ks * 32 + (lt >> 1) * 16;
                ldsm4(addr, a[i][0], a[i][1], a[i][2], a[i][3]);
            }
            uint32_t b[4][2];
            #pragma unroll
            for (int jp = 0; jp < 2; jp++) {
                const uint32_t addr = bs
                    + (uint32_t)(wn + jp * 16 + (lt >> 1) * 8 + lrow) * 80
                    + ks * 32 + (lt & 1) * 16;
                ldsm4(addr, b[2 * jp][0], b[2 * jp][1],
                            b[2 * jp + 1][0], b[2 * jp + 1][1]);
            }
            #pragma unroll
            for (int i = 0; i < 4; i++)
                #pragma unroll
                for (int j = 0; j < 4; j++)
                    MMA16816(acc[i][j], a[i][0], a[i][1], a[i][2], a[i][3],
                             b[j][0], b[j][1]);
        }
    }
    #undef ISSUE_CHUNK

    const int lr = lane >> 2;
    const int lk = lane & 3;
    #pragma unroll
    for (int i = 0; i < 4; i++) {
        #pragma unroll
        for (int j = 0; j < 4; j++) {
            const int row0 = bm + wm + i * 16 + lr;
            const int col  = bn + wn + j * 8 + lk * 2;
            #pragma unroll
            for (int hrow = 0; hrow < 2; hrow++) {
                const int row = row0 + hrow * 8;
                float ox = acc[i][j][hrow * 2 + 0] + bias[col + 0];
                float oy = acc[i][j][hrow * 2 + 1] + bias[col + 1];
                if (EPI == 1 || EPI == 3) {
                    if (EPI == 1) { ox = gelu_exact(ox); oy = gelu_exact(oy); }
                    __half2* dst = reinterpret_cast<__half2*>(
                        reinterpret_cast<__half*>(Cv) + (size_t)row * N + col);
                    *dst = __floats2half2_rn(ox, oy);
                } else {
                    if (EPI == 2) {
                        const float2 r2 = *reinterpret_cast<const float2*>(
                            res + (size_t)row * N + col);
                        ox += r2.x; oy += r2.y;
                    }
                    float2 o; o.x = ox; o.y = oy;
                    *reinterpret_cast<float2*>(
                        reinterpret_cast<float*>(Cv) + (size_t)row * N + col) = o;
                }
            }
        }
    }
}

// ---------------- LayerNorm (half output) -----------------------------------
__global__ __launch_bounds__(256) void ln_kernel(
    const float* __restrict__ x, const float* __restrict__ g,
    const float* __restrict__ b, __half* __restrict__ out)
{
    const int row = blockIdx.x;
    const int t   = threadIdx.x;
    const float4 v = reinterpret_cast<const float4*>(x + (size_t)row * Dm)[t];

    float s  = v.x + v.y + v.z + v.w;
    float s2 = v.x * v.x + v.y * v.y + v.z * v.z + v.w * v.w;

    __shared__ float red[16];
    #pragma unroll
    for (int o = 16; o; o >>= 1) {
        s  += __shfl_xor_sync(0xffffffffu, s,  o);
        s2 += __shfl_xor_sync(0xffffffffu, s2, o);
    }
    const int w = t >> 5, l = t & 31;
    if (l == 0) { red[w] = s; red[w + 8] = s2; }
    __syncthreads();
    if (w == 0) {
        float a  = (l < 8) ? red[l]     : 0.f;
        float a2 = (l < 8) ? red[l + 8] : 0.f;
        #pragma unroll
        for (int o = 4; o; o >>= 1) {
            a  += __shfl_xor_sync(0xffffffffu, a,  o);
            a2 += __shfl_xor_sync(0xffffffffu, a2, o);
        }
        if (l == 0) { red[0] = a; red[1] = a2; }
    }
    __syncthreads();

    const float mean = red[0] * (1.f / Dm);
    const float var  = red[1] * (1.f / Dm) - mean * mean;
    const float rs   = rsqrtf(var + 1e-5f);

    const float4 gg = reinterpret_cast<const float4*>(g)[t];
    const float4 bb = reinterpret_cast<const float4*>(b)[t];
    const float o0 = (v.x - mean) * rs * gg.x + bb.x;
    const float o1 = (v.y - mean) * rs * gg.y + bb.y;
    const float o2 = (v.z - mean) * rs * gg.z + bb.z;
    const float o3 = (v.w - mean) * rs * gg.w + bb.w;

    __half2* dst = reinterpret_cast<__half2*>(out + (size_t)row * Dm) + t * 2;
    dst[0] = __floats2half2_rn(o0, o1);
    dst[1] = __floats2half2_rn(o2, o3);
}

// ---------------- tensor-core block-sparse flash attention ------------------
#define QST 72   // smem row stride in halves (144 B)
#define ATTN_SMEM (3 * 128 * QST * 2)

__global__ __launch_bounds__(256) void attn_kernel(
    const __half* __restrict__ qkv, const int* __restrict__ layout,
    __half* __restrict__ ctx)
{
    extern __shared__ __half smh[];
    __half* sQ = smh;
    __half* sK = smh + 128 * QST;
    __half* sV = smh + 256 * QST;
    const uint32_t sQa = smem_u32(sQ);
    const uint32_t sKa = smem_u32(sK);
    const uint32_t sVa = smem_u32(sV);

    const int ib  = blockIdx.x;
    const int hh  = blockIdx.y;
    const int bb  = blockIdx.z;
    const int tid = threadIdx.x;
    const int w    = tid >> 5, lane = tid & 31;
    const int lr   = lane >> 2, lk = lane & 3;
    const int lt   = lane >> 3, lrow = lane & 7;
    const int wm   = w * 16;

    const size_t qrow0 = (size_t)(bb * Sseq + ib * BLKs);

    for (int f = tid; f < 1024; f += 256) {
        const int row = f >> 3, seg = f & 7;
        *reinterpret_cast<uint4*>(sQ + row * QST + seg * 8) =
            *reinterpret_cast<const uint4*>(qkv + (qrow0 + row) * QKV3 + hh * 64 + seg * 8);
    }
    __syncthreads();

    uint32_t qf[4][4];
    #pragma unroll
    for (int ks = 0; ks < 4; ks++) {
        const uint32_t addr = sQa + (uint32_t)(wm + (lt & 1) * 8 + lrow) * 144
                            + ks * 32 + (lt >> 1) * 16;
        ldsm4(addr, qf[ks][0], qf[ks][1], qf[ks][2], qf[ks][3]);
    }

    float m0 = -1e30f, m1 = -1e30f, l0 = 0.f, l1 = 0.f;
    float octx[8][4];
    #pragma unroll
    for (int jn = 0; jn < 8; jn++)
        #pragma unroll
        for (int c = 0; c < 4; c++) octx[jn][c] = 0.f;

    for (int j = 0; j <= ib; j++) {
        if (!layout[(hh * NBl + ib) * NBl + j]) continue;

        __syncthreads();
        const size_t krow0 = (size_t)(bb * Sseq + j * BLKs);
        for (int f = tid; f < 1024; f += 256) {
            const int row = f >> 3, seg = f & 7;
            const __half* src = qkv + (krow0 + row) * QKV3 + hh * 64 + seg * 8;
            *reinterpret_cast<uint4*>(sK + row * QST + seg * 8) =
                *reinterpret_cast<const uint4*>(src + Dm);
            *reinterpret_cast<uint4*>(sV + row * QST + seg * 8) =
                *reinterpret_cast<const uint4*>(src + 2 * Dm);
        }
        __syncthreads();

        float sacc[16][4];
        #pragma unroll
        for (int jf = 0; jf < 16; jf++)
            #pragma unroll
            for (int c = 0; c < 4; c++) sacc[jf][c] = 0.f;

        #pragma unroll
        for (int ks = 0; ks < 4; ks++) {
            #pragma unroll
            for (int jp = 0; jp < 8; jp++) {
                uint32_t b0, b1, b2, b3;
                const uint32_t addr = sKa
                    + (uint32_t)(jp * 16 + (lt >> 1) * 8 + lrow) * 144
                    + ks * 32 + (lt & 1) * 16;
                ldsm4(addr, b0, b1, b2, b3);
                MMA16816(sacc[2 * jp],     qf[ks][0], qf[ks][1], qf[ks][2], qf[ks][3], b0, b1);
                MMA16816(sacc[2 * jp + 1], qf[ks][0], qf[ks][1], qf[ks][2], qf[ks][3], b2, b3);
            }
        }

        const int r0 = wm + lr, r1 = wm + lr + 8;
        #pragma unroll
        for (int jf = 0; jf < 16; jf++) {
            #pragma unroll
            for (int c = 0; c < 4; c++) sacc[jf][c] *= 0.125f;
            if (j == ib) {
                const int c0 = jf * 8 + lk * 2, c1 = c0 + 1;
                if (c0 > r0) sacc[jf][0] = -1e9f;
                if (c1 > r0) sacc[jf][1] = -1e9f;
                if (c0 > r1) sacc[jf][2] = -1e9f;
                if (c1 > r1) sacc[jf][3] = -1e9f;
            }
        }

        float bm0 = -1e30f, bm1 = -1e30f;
        #pragma unroll
        for (int jf = 0; jf < 16; jf++) {
            bm0 = fmaxf(bm0, fmaxf(sacc[jf][0], sacc[jf][1]));
            bm1 = fmaxf(bm1, fmaxf(sacc[jf][2], sacc[jf][3]));
        }
        bm0 = fmaxf(bm0, __shfl_xor_sync(0xffffffffu, bm0, 1));
        bm0 = fmaxf(bm0, __shfl_xor_sync(0xffffffffu, bm0, 2));
        bm1 = fmaxf(bm1, __shfl_xor_sync(0xffffffffu, bm1, 1));
        bm1 = fmaxf(bm1, __shfl_xor_sync(0xffffffffu, bm1, 2));

        const float nm0 = fmaxf(m0, bm0), nm1 = fmaxf(m1, bm1);
        const float cr0 = __expf(m0 - nm0), cr1 = __expf(m1 - nm1);

        float s0 = 0.f, s1 = 0.f;
        uint32_t ph[16][2];
        #pragma unroll
        for (int jf = 0; jf < 16; jf++) {
            const float p00 = __expf(sacc[jf][0] - nm0);
            const float p01 = __expf(sacc[jf][1] - nm0);
            const float p10 = __expf(sacc[jf][2] - nm1);
            const float p11 = __expf(sacc[jf][3] - nm1);
            s0 += p00 + p01; s1 += p10 + p11;
            ph[jf][0] = h2_as_u32(__floats2half2_rn(p00, p01));
            ph[jf][1] = h2_as_u32(__floats2half2_rn(p10, p11));
        }
        s0 += __shfl_xor_sync(0xffffffffu, s0, 1);
        s0 += __shfl_xor_sync(0xffffffffu, s0, 2);
        s1 += __shfl_xor_sync(0xffffffffu, s1, 1);
        s1 += __shfl_xor_sync(0xffffffffu, s1, 2);

        l0 = l0 * cr0 + s0;
        l1 = l1 * cr1 + s1;
        #pragma unroll
        for (int jn = 0; jn < 8; jn++) {
            octx[jn][0] *= cr0; octx[jn][1] *= cr0;
            octx[jn][2] *= cr1; octx[jn][3] *= cr1;
        }

        #pragma unroll
        for (int kk = 0; kk < 8; kk++) {
            const uint32_t a0 = ph[2 * kk][0],     a1 = ph[2 * kk][1];
            const uint32_t a2 = ph[2 * kk + 1][0], a3 = ph[2 * kk + 1][1];
            #pragma unroll
            for (int jp = 0; jp < 4; jp++) {
                uint32_t b0, b1, b2, b3;
                const uint32_t addr = sVa
                    + (uint32_t)(kk * 16 + (lt & 1) * 8 + lrow) * 144
                    + (uint32_t)(jp * 16 + (lt >> 1) * 8) * 2;
                ldsm4t(addr, b0, b1, b2, b3);
                MMA16816(octx[2 * jp],     a0, a1, a2, a3, b0, b1);
                MMA16816(octx[2 * jp + 1], a0, a1, a2, a3, b2, b3);
            }
        }
        m0 = nm0; m1 = nm1;
    }

    const float inv0 = 1.f / l0, inv1 = 1.f / l1;
    __half* base0 = ctx + (qrow0 + wm + lr) * Dm + hh * 64;
    __half* base1 = ctx + (qrow0 + wm + lr + 8) * Dm + hh * 64;
    #pragma unroll
    for (int jn = 0; jn < 8; jn++) {
        const int col = jn * 8 + lk * 2;
        *reinterpret_cast<__half2*>(base0 + col) =
            __floats2half2_rn(octx[jn][0] * inv0, octx[jn][1] * inv0);
        *reinterpret_cast<__half2*>(base1 + col) =
            __floats2half2_rn(octx[jn][2] * inv1, octx[jn][3] * inv1);
    }
}

// ---------------------------------------------------------------------------
extern "C" void kernel_launch(void* const* d_in, const int* in_sizes, int n_in,
                              void* d_out, int out_size)
{
    (void)in_sizes; (void)n_in; (void)out_size;
    const float* x     = (const float*)d_in[0];
    const float* ln1_g = (const float*)d_in[1];
    const float* ln1_b = (const float*)d_in[2];
    const float* Wq    = (const float*)d_in[3];
    const float* bq    = (const float*)d_in[4];
    const float* Wk    = (const float*)d_in[5];
    const float* bk    = (const float*)d_in[6];
    const float* Wv    = (const float*)d_in[7];
    const float* bv    = (const float*)d_in[8];
    const float* Wo    = (const float*)d_in[9];
    const float* bo    = (const float*)d_in[10];
    const float* ln2_g = (const float*)d_in[11];
    const float* ln2_b = (const float*)d_in[12];
    const float* W1    = (const float*)d_in[13];
    const float* b1    = (const float*)d_in[14];
    const float* W2    = (const float*)d_in[15];
    const float* b2    = (const float*)d_in[16];
    const int*   lay   = (const int*)d_in[17];
    float* out = (float*)d_out;

    __half *h, *qkv, *ctx, *h2, *ff, *wqkv, *wo, *w1, *w2;
    float  *x1, *bqkv;
    cudaGetSymbolAddress((void**)&h,    g_h);
    cudaGetSymbolAddress((void**)&qkv,  g_qkv);
    cudaGetSymbolAddress((void**)&ctx,  g_ctx);
    cudaGetSymbolAddress((void**)&x1,   g_x1);
    cudaGetSymbolAddress((void**)&h2,   g_h2);
    cudaGetSymbolAddress((void**)&ff,   g_ff);
    cudaGetSymbolAddress((void**)&wqkv, g_wqkv);
    cudaGetSymbolAddress((void**)&wo,   g_wo);
    cudaGetSymbolAddress((void**)&w1,   g_w1);
    cudaGetSymbolAddress((void**)&w2,   g_w2);
    cudaGetSymbolAddress((void**)&bqkv, g_bqkv);

    cudaFuncSetAttribute(attn_kernel,
                         cudaFuncAttributeMaxDynamicSharedMemorySize, ATTN_SMEM);
    cudaFuncSetAttribute(mma_gemm<1>,
                         cudaFuncAttributeMaxDynamicSharedMemorySize, MMA_SMEM);
    cudaFuncSetAttribute(mma_gemm<2>,
                         cudaFuncAttributeMaxDynamicSharedMemorySize, MMA_SMEM);
    cudaFuncSetAttribute(mma_gemm<3>,
                         cudaFuncAttributeMaxDynamicSharedMemorySize, MMA_SMEM);

    // 0) fused weight prep (1 launch) + bias concat
    wprep_all<<<12288, 256>>>(Wq, Wk, Wv, Wo, W1, W2, wqkv, wo, w1, w2);
    bprep<<<(QKV3 + 255) / 256, 256>>>(bq, bk, bv, bqkv);

    // 1) ln1 -> half h
    ln_kernel<<<Mrows, 256>>>(x, ln1_g, ln1_b, h);

    // 2) fused QKV projection (half out)
    mma_gemm<3><<<dim3(QKV3 / 128, Mrows / 128), 256, MMA_SMEM>>>(
        h, wqkv, bqkv, nullptr, qkv, Mrows, QKV3, Dm);

    // 3) tensor-core block-sparse attention -> half ctx
    attn_kernel<<<dim3(NBl, Hh, Bsz), 256, ATTN_SMEM>>>(qkv, lay, ctx);

    // 4) output projection + residual (float x1)   <-- ncu captures this (#6)
    dim3 g1(Dm / 128, Mrows / 128);
    mma_gemm<2><<<g1, 256, MMA_SMEM>>>(ctx, wo, bo, x, x1, Mrows, Dm, Dm);

    // 5) ln2 -> half h2
    ln_kernel<<<Mrows, 256>>>(x1, ln2_g, ln2_b, h2);

    // 6) MLP
    dim3 g2(Dff / 128, Mrows / 128);
    mma_gemm<1><<<g2, 256, MMA_SMEM>>>(h2, w1, b1, nullptr, ff, Mrows, Dff, Dm);
    mma_gemm<2><<<g1, 256, MMA_SMEM>>>(ff, w2, b2, x1, out, Mrows, Dm, Dff);
}